// round 3
// baseline (speedup 1.0000x reference)
#include <cuda_runtime.h>

// Problem shapes (fixed by the dataset)
constexpr int B  = 8;
constexpr int H  = 512, W  = 512;
constexpr int HO = 1024, WO = 1024;
constexpr int FPY = 514;             // padded rows: y coords -1..512
constexpr int FPX = 516;             // padded row stride (514 valid + 2 pad, float4-aligned)
constexpr int TPR = 129;             // fix threads per row (129*4 = 516)
constexpr int NPIX = B * HO * WO;    // 8388608 output pixels
constexpr int NFIXT = B * FPY * TPR;

// Precomputed "fixed" depth map, padded domain. 8*514*516*4 B = 8.49 MB (L2-resident).
__device__ float4 g_fix4[B * FPY * (FPX / 4)];

// Load 6 input floats covering columns [px0-2, px0+3] of `row` (0 if OOB).
__device__ __forceinline__ void load_row6(const float* __restrict__ img, int row,
                                          int px0, float v[6]) {
    if ((unsigned)row >= (unsigned)H) {
        v[0] = v[1] = v[2] = v[3] = v[4] = v[5] = 0.0f;
        return;
    }
    const float* rp = img + row * W;
    if (px0 >= 4 && px0 <= 508) {
        float4 a = *(const float4*)(rp + px0 - 4);
        float4 b = *(const float4*)(rp + px0);
        v[0] = a.z; v[1] = a.w;
        v[2] = b.x; v[3] = b.y; v[4] = b.z; v[5] = b.w;
    } else {
#pragma unroll
        for (int i = 0; i < 6; i++) {
            int c = px0 - 2 + i;
            v[i] = ((unsigned)c < (unsigned)W) ? __ldg(rp + c) : 0.0f;
        }
    }
}

// Pass 1: first-valid candidate among the 9 offsets in reference order:
//   (0,0), (-1,-1),(-1,0),(-1,1),(0,-1),(0,1),(1,-1),(1,0),(1,1)
__global__ void __launch_bounds__(256) fix_kernel(const float* __restrict__ depth) {
    int idx = blockIdx.x * blockDim.x + threadIdx.x;
    if (idx >= NFIXT) return;
    int row = idx / TPR;
    int t   = idx - row * TPR;
    int b   = row / FPY;
    int py  = row - b * FPY;
    int px0 = t * 4;
    int y   = py - 1;

    const float* img = depth + b * (H * W);

    float m1[6], r0[6], p1[6];
    load_row6(img, y - 1, px0, m1);
    load_row6(img, y,     px0, r0);
    load_row6(img, y + 1, px0, p1);

    float4 o;
    float* op = &o.x;
#pragma unroll
    for (int j = 0; j < 4; j++) {
        float c[9] = { r0[j + 1],
                       m1[j], m1[j + 1], m1[j + 2],
                       r0[j],            r0[j + 2],
                       p1[j], p1[j + 1], p1[j + 2] };
        float v = 0.0f;
#pragma unroll
        for (int k = 8; k >= 0; k--) {
            if (c[k] != 0.0f) v = c[k];      // first-valid via reverse last-write
        }
        op[j] = v;
    }
    g_fix4[row * (FPX / 4) + t] = o;
}

// Pass 2: 8 pixels per thread; all 8 gather addresses computed first, then 8
// independent loads batched for max MLP, then stores.
__global__ void __launch_bounds__(256) sample_kernel(const float4* __restrict__ grid,
                                                     float4* __restrict__ out) {
    int t = blockIdx.x * blockDim.x + threadIdx.x;
    if (t >= NPIX / 8) return;

    float4 g0 = __ldcs(grid + 4 * t);
    float4 g1 = __ldcs(grid + 4 * t + 1);
    float4 g2 = __ldcs(grid + 4 * t + 2);
    float4 g3 = __ldcs(grid + 4 * t + 3);

    int b = t >> 17;                          // 8 px never span batches (HO*WO = 1<<20)
    const float* fixp = (const float*)g_fix4 + b * (FPY * FPX);

    float gx[8] = {g0.x, g0.z, g1.x, g1.z, g2.x, g2.z, g3.x, g3.z};
    float gy[8] = {g0.y, g0.w, g1.y, g1.w, g2.y, g2.w, g3.y, g3.w};

    int   off[8];
    bool  inb[8];
#pragma unroll
    for (int i = 0; i < 8; i++) {
        // ((g+1)*0.5)*511 == round_fp32(g+1) * 255.5 exactly (×0.5 exact);
        // __float2int_rn = ties-to-even = jnp.round
        float xf = __fmul_rn(__fadd_rn(gx[i], 1.0f), 255.5f);
        float yf = __fmul_rn(__fadd_rn(gy[i], 1.0f), 255.5f);
        int ix = __float2int_rn(xf) + 1;      // padded coords
        int iy = __float2int_rn(yf) + 1;
        inb[i] = ((unsigned)ix < 514u) & ((unsigned)iy < 514u);
        off[i] = iy * FPX + ix;
    }

    float v[8];
#pragma unroll
    for (int i = 0; i < 8; i++) {
        v[i] = inb[i] ? __ldg(fixp + off[i]) : 0.0f;   // predicated LDG, all independent
    }

    float4 oa = {v[0], v[1], v[2], v[3]};
    float4 ob = {v[4], v[5], v[6], v[7]};
    __stcs(out + 2 * t, oa);
    __stcs(out + 2 * t + 1, ob);
}

extern "C" void kernel_launch(void* const* d_in, const int* in_sizes, int n_in,
                              void* d_out, int out_size) {
    const float*  depth = (const float*)d_in[0];   // (B,1,H,W) f32
    const float4* grid  = (const float4*)d_in[1];  // (B,Ho,Wo,2) f32 as float4
    float4*       out   = (float4*)d_out;          // (B,1,Ho,Wo) f32 as float4

    fix_kernel<<<(NFIXT + 255) / 256, 256>>>(depth);
    sample_kernel<<<(NPIX / 8 + 255) / 256, 256>>>(grid, out);
}

// round 4
// speedup vs baseline: 1.2183x; 1.2183x over previous
#include <cuda_runtime.h>

// Problem shapes (fixed by the dataset)
constexpr int B  = 8;
constexpr int H  = 512, W  = 512;
constexpr int HO = 1024, WO = 1024;
constexpr int FPY = 514;             // padded rows: y coords -1..512
constexpr int FPX = 516;             // padded row stride (514 valid + 2 pad, float4-aligned)
constexpr int TPR = 129;             // fix threads per row (129*4 = 516)
constexpr int NPIX = B * HO * WO;    // 8388608 output pixels
constexpr int NQUAD = NPIX / 4;      // 2097152 output quads
constexpr int NFIXT = B * FPY * TPR;

constexpr int SAMPLE_BLOCKS  = 148 * 16;   // persistent-ish grid-stride
constexpr int SAMPLE_THREADS = 256;

// Precomputed "fixed" depth map, padded domain. 8*514*516*4 B = 8.49 MB (L2-resident).
__device__ float4 g_fix4[B * FPY * (FPX / 4)];

// Load 6 input floats covering columns [px0-2, px0+3] of `row` (0 if OOB).
__device__ __forceinline__ void load_row6(const float* __restrict__ img, int row,
                                          int px0, float v[6]) {
    if ((unsigned)row >= (unsigned)H) {
        v[0] = v[1] = v[2] = v[3] = v[4] = v[5] = 0.0f;
        return;
    }
    const float* rp = img + row * W;
    if (px0 >= 4 && px0 <= 508) {
        float4 a = *(const float4*)(rp + px0 - 4);
        float4 b = *(const float4*)(rp + px0);
        v[0] = a.z; v[1] = a.w;
        v[2] = b.x; v[3] = b.y; v[4] = b.z; v[5] = b.w;
    } else {
#pragma unroll
        for (int i = 0; i < 6; i++) {
            int c = px0 - 2 + i;
            v[i] = ((unsigned)c < (unsigned)W) ? __ldg(rp + c) : 0.0f;
        }
    }
}

// Pass 1: first-valid candidate among the 9 offsets in reference order:
//   (0,0), (-1,-1),(-1,0),(-1,1),(0,-1),(0,1),(1,-1),(1,0),(1,1)
__global__ void __launch_bounds__(256) fix_kernel(const float* __restrict__ depth) {
    int idx = blockIdx.x * blockDim.x + threadIdx.x;
    if (idx >= NFIXT) return;
    int row = idx / TPR;
    int t   = idx - row * TPR;
    int b   = row / FPY;
    int py  = row - b * FPY;
    int px0 = t * 4;
    int y   = py - 1;

    const float* img = depth + b * (H * W);

    float m1[6], r0[6], p1[6];
    load_row6(img, y - 1, px0, m1);
    load_row6(img, y,     px0, r0);
    load_row6(img, y + 1, px0, p1);

    float4 o;
    float* op = &o.x;
#pragma unroll
    for (int j = 0; j < 4; j++) {
        float c[9] = { r0[j + 1],
                       m1[j], m1[j + 1], m1[j + 2],
                       r0[j],            r0[j + 2],
                       p1[j], p1[j + 1], p1[j + 2] };
        float v = 0.0f;
#pragma unroll
        for (int k = 8; k >= 0; k--) {
            if (c[k] != 0.0f) v = c[k];      // first-valid via reverse last-write
        }
        op[j] = v;
    }
    g_fix4[row * (FPX / 4) + t] = o;
}

// Process one quad (4 output pixels) given its two grid float4s.
__device__ __forceinline__ void do_quad(int q, float4 ga, float4 gb,
                                        float4* __restrict__ out) {
    int b = q >> 18;                          // quads never span batches (HO*WO = 1<<20)
    const float* fixp = (const float*)g_fix4 + b * (FPY * FPX);

    float gx[4] = {ga.x, ga.z, gb.x, gb.z};
    float gy[4] = {ga.y, ga.w, gb.y, gb.w};

    float v[4];
#pragma unroll
    for (int i = 0; i < 4; i++) {
        // ((g+1)*0.5)*511 == round_fp32(g+1) * 255.5 exactly (×0.5 exact);
        // __float2int_rn = ties-to-even = jnp.round
        float xf = __fmul_rn(__fadd_rn(gx[i], 1.0f), 255.5f);
        float yf = __fmul_rn(__fadd_rn(gy[i], 1.0f), 255.5f);
        int ix = __float2int_rn(xf) + 1;      // padded coords
        int iy = __float2int_rn(yf) + 1;
        bool inb = ((unsigned)ix < 514u) & ((unsigned)iy < 514u);
        v[i] = inb ? __ldg(fixp + iy * FPX + ix) : 0.0f;
    }

    float4 o = {v[0], v[1], v[2], v[3]};
    __stcs(out + q, o);
}

// Pass 2: grid-stride loop, 4 px/iteration, next iteration's grid prefetched
// while current gathers are in flight.
__global__ void __launch_bounds__(SAMPLE_THREADS)
sample_kernel(const float4* __restrict__ grid, float4* __restrict__ out) {
    const int stride = SAMPLE_BLOCKS * SAMPLE_THREADS;
    int q = blockIdx.x * SAMPLE_THREADS + threadIdx.x;
    if (q >= NQUAD) return;

    float4 ga = __ldcs(grid + 2 * q);
    float4 gb = __ldcs(grid + 2 * q + 1);

    int qn = q + stride;
    while (qn < NQUAD) {
        float4 na = __ldcs(grid + 2 * qn);     // prefetch next (overlaps gathers below)
        float4 nb = __ldcs(grid + 2 * qn + 1);
        do_quad(q, ga, gb, out);
        q = qn; qn += stride;
        ga = na; gb = nb;
    }
    do_quad(q, ga, gb, out);
}

extern "C" void kernel_launch(void* const* d_in, const int* in_sizes, int n_in,
                              void* d_out, int out_size) {
    const float*  depth = (const float*)d_in[0];   // (B,1,H,W) f32
    const float4* grid  = (const float4*)d_in[1];  // (B,Ho,Wo,2) f32 as float4
    float4*       out   = (float4*)d_out;          // (B,1,Ho,Wo) f32 as float4

    fix_kernel<<<(NFIXT + 255) / 256, 256>>>(depth);
    sample_kernel<<<SAMPLE_BLOCKS, SAMPLE_THREADS>>>(grid, out);
}

// round 5
// speedup vs baseline: 1.2194x; 1.0009x over previous
#include <cuda_runtime.h>

// Problem shapes (fixed by the dataset)
constexpr int B  = 8;
constexpr int H  = 512, W  = 512;
constexpr int HO = 1024, WO = 1024;
constexpr int FPY = 514;             // padded rows: y coords -1..512
constexpr int FPX = 516;             // padded row stride (514 valid + 2 pad, float4-aligned)
constexpr int TPR = 129;             // fix col-groups per row (129*4 = 516)
constexpr int NPIX = B * HO * WO;    // 8388608 output pixels
constexpr int NQUAD = NPIX / 4;      // 2097152 output quads

constexpr int RPT    = 4;                    // fix rows per thread (rolling window)
constexpr int STRIPS = (FPY + RPT - 1) / RPT;  // 129
constexpr int NFIXT  = B * STRIPS * TPR;     // 133128 fix threads

constexpr int SAMPLE_BLOCKS  = 888;          // 6 CTAs/SM, single persistent wave
constexpr int SAMPLE_THREADS = 256;

// Precomputed "fixed" depth map, padded domain. 8*514*516*4 B = 8.49 MB (L2-resident).
__device__ float4 g_fix4[B * FPY * (FPX / 4)];

// Load 6 input floats covering columns [px0-2, px0+3] of `row` (0 if OOB).
__device__ __forceinline__ void load_row6(const float* __restrict__ img, int row,
                                          int px0, float v[6]) {
    if ((unsigned)row >= (unsigned)H) {
        v[0] = v[1] = v[2] = v[3] = v[4] = v[5] = 0.0f;
        return;
    }
    const float* rp = img + row * W;
    if (px0 >= 4 && px0 <= 508) {
        float4 a = *(const float4*)(rp + px0 - 4);
        float4 b = *(const float4*)(rp + px0);
        v[0] = a.z; v[1] = a.w;
        v[2] = b.x; v[3] = b.y; v[4] = b.z; v[5] = b.w;
    } else {
#pragma unroll
        for (int i = 0; i < 6; i++) {
            int c = px0 - 2 + i;
            v[i] = ((unsigned)c < (unsigned)W) ? __ldg(rp + c) : 0.0f;
        }
    }
}

// Pass 1: first-valid candidate among the 9 offsets in reference order:
//   (0,0), (-1,-1),(-1,0),(-1,1),(0,-1),(0,1),(1,-1),(1,0),(1,1)
// Each thread handles 4 columns x RPT rows with a 3-row rolling window.
__global__ void __launch_bounds__(256) fix_kernel(const float* __restrict__ depth) {
    int idx = blockIdx.x * blockDim.x + threadIdx.x;
    if (idx >= NFIXT) return;
    int t     = idx % TPR;
    int rest  = idx / TPR;
    int strip = rest % STRIPS;
    int b     = rest / STRIPS;
    int px0   = t * 4;
    int py0   = strip * RPT;
    int y0    = py0 - 1;            // first padded y coord of this strip

    const float* img = depth + b * (H * W);

    float rm[6], r0[6], rp[6];
    load_row6(img, y0 - 1, px0, rm);
    load_row6(img, y0,     px0, r0);

#pragma unroll
    for (int r = 0; r < RPT; r++) {
        int py = py0 + r;
        load_row6(img, y0 + r + 1, px0, rp);
        if (py < FPY) {
            float4 o;
            float* op = &o.x;
#pragma unroll
            for (int j = 0; j < 4; j++) {
                float c[9] = { r0[j + 1],
                               rm[j], rm[j + 1], rm[j + 2],
                               r0[j],            r0[j + 2],
                               rp[j], rp[j + 1], rp[j + 2] };
                float v = 0.0f;
#pragma unroll
                for (int k = 8; k >= 0; k--) {
                    if (c[k] != 0.0f) v = c[k];   // first-valid via reverse last-write
                }
                op[j] = v;
            }
            g_fix4[(b * FPY + py) * (FPX / 4) + t] = o;
        }
#pragma unroll
        for (int i = 0; i < 6; i++) { rm[i] = r0[i]; r0[i] = rp[i]; }  // renamed by unroll
    }
}

// Issue 4 independent gathers for quad q (grid values ga,gb); results into v[4].
__device__ __forceinline__ void issue_quad(int q, float4 ga, float4 gb, float v[4]) {
    int b = q >> 18;                          // quads never span batches (HO*WO = 1<<20)
    const float* fixp = (const float*)g_fix4 + b * (FPY * FPX);
    float gx[4] = {ga.x, ga.z, gb.x, gb.z};
    float gy[4] = {ga.y, ga.w, gb.y, gb.w};
#pragma unroll
    for (int i = 0; i < 4; i++) {
        // ((g+1)*0.5)*511 == round_fp32(g+1) * 255.5 exactly (×0.5 exact);
        // __float2int_rn = ties-to-even = jnp.round
        float xf = __fmul_rn(__fadd_rn(gx[i], 1.0f), 255.5f);
        float yf = __fmul_rn(__fadd_rn(gy[i], 1.0f), 255.5f);
        int ix = __float2int_rn(xf) + 1;      // padded coords
        int iy = __float2int_rn(yf) + 1;
        bool inb = ((unsigned)ix < 514u) & ((unsigned)iy < 514u);
        v[i] = inb ? __ldg(fixp + iy * FPX + ix) : 0.0f;
    }
}

__device__ __forceinline__ void store_quad(int q, const float v[4],
                                           float4* __restrict__ out) {
    float4 o = {v[0], v[1], v[2], v[3]};
    __stcs(out + q, o);
}

// Pass 2: grid-stride, depth-2 software pipeline. Stage i+1's gathers are
// issued before stage i's results are consumed, so each gather gets a full
// iteration of slack; at most 8 gathers in flight, issued staggered (not one
// burst — avoids the R3 L1tex-queue pileup). Manually unrolled x2 so no
// register copies of in-flight values.
__global__ void __launch_bounds__(SAMPLE_THREADS)
sample_kernel(const float4* __restrict__ grid, float4* __restrict__ out) {
    const int stride = SAMPLE_BLOCKS * SAMPLE_THREADS;
    int qA = blockIdx.x * SAMPLE_THREADS + threadIdx.x;
    if (qA >= NQUAD) return;

    float4 gA0 = __ldcs(grid + 2 * qA);
    float4 gA1 = __ldcs(grid + 2 * qA + 1);
    float vA[4];
    issue_quad(qA, gA0, gA1, vA);

    int qB = qA + stride;
    bool hasB = qB < NQUAD;
    float4 gB0, gB1;
    if (hasB) { gB0 = __ldcs(grid + 2 * qB); gB1 = __ldcs(grid + 2 * qB + 1); }

    while (hasB) {
        // ---- half 1: B's gathers in, then retire A ----
        int qC = qB + stride;
        bool hasC = qC < NQUAD;
        if (hasC) { gA0 = __ldcs(grid + 2 * qC); gA1 = __ldcs(grid + 2 * qC + 1); }
        float vB[4];
        issue_quad(qB, gB0, gB1, vB);
        store_quad(qA, vA, out);              // vA issued one full stage ago
        if (!hasC) { store_quad(qB, vB, out); return; }

        // ---- half 2: C's gathers in, then retire B ----
        int qD = qC + stride;
        bool hasD = qD < NQUAD;
        if (hasD) { gB0 = __ldcs(grid + 2 * qD); gB1 = __ldcs(grid + 2 * qD + 1); }
        issue_quad(qC, gA0, gA1, vA);
        store_quad(qB, vB, out);
        if (!hasD) { store_quad(qC, vA, out); return; }

        qA = qC; qB = qD; hasB = true;
    }
    store_quad(qA, vA, out);
}

extern "C" void kernel_launch(void* const* d_in, const int* in_sizes, int n_in,
                              void* d_out, int out_size) {
    const float*  depth = (const float*)d_in[0];   // (B,1,H,W) f32
    const float4* grid  = (const float4*)d_in[1];  // (B,Ho,Wo,2) f32 as float4
    float4*       out   = (float4*)d_out;          // (B,1,Ho,Wo) f32 as float4

    fix_kernel<<<(NFIXT + 255) / 256, 256>>>(depth);
    sample_kernel<<<SAMPLE_BLOCKS, SAMPLE_THREADS>>>(grid, out);
}